// round 10
// baseline (speedup 1.0000x reference)
#include <cuda_runtime.h>

#define NB      64
#define NT      1024
#define MAXLAG  256
#define CBLK    16                   // blocks per batch
#define NWARP   8                    // warps per block
#define POSW    8                    // positions per warp
#define BLKP    (NWARP * POSW)       // 64 positions per block
#define SWIN    320                  // staged window (float2): 64 + 255 + 1

typedef unsigned long long ull;

__device__ float        g_partial[NB * CBLK * MAXLAG];   // [b][cb][lag]
__device__ float        g_pt[NB];
__device__ unsigned int g_cnt[NB];   // zero-init; reset by last observer
__device__ unsigned int g_cnt2;      // zero-init; reset by last observer

// lengths may arrive as int64 or int32 (jax x64 config). Values in [512,1024];
// little-endian int64 => word[1] (high half of elem 0) == 0.
__device__ __forceinline__ int load_length(const unsigned int* lp, int b) {
    bool is64 = (lp[1] == 0u);
    return is64 ? (int)lp[2 * b] : (int)lp[b];
}

// XOR swizzle on float2 index (flips low 4 bits only; stays in 16-group).
__device__ __forceinline__ int swz(int q) { return q ^ ((q >> 4) & 15); }

__device__ __forceinline__ unsigned int atom_inc_acqrel(unsigned int* p) {
    unsigned int old;
    asm volatile("atom.acq_rel.gpu.global.add.u32 %0, [%1], 1;"
                 : "=r"(old) : "l"(p) : "memory");
    return old;
}

#define NEG1C 0xBF800000BF800000ull

// Predicated pair groups: if (kc < kth) { d_m = w - b_m; A_m += d_m*d_m }.
// One setp per group, predicated f32x2 FMAs, ZERO branches.
__device__ __forceinline__ void g1(ull& A0, ull b0, ull w, int kc, int kth) {
    asm("{.reg .pred p; .reg .b64 d0;\n\t"
        "setp.lt.s32 p, %4, %5;\n\t"
        "@p fma.rn.f32x2 d0, %2, %3, %1;\n\t"
        "@p fma.rn.f32x2 %0, d0, d0, %0;}\n"
        : "+l"(A0)
        : "l"(w), "l"(b0), "l"(NEG1C), "r"(kc), "r"(kth));
}
__device__ __forceinline__ void g2(ull& A0, ull& A1, ull b0, ull b1,
                                   ull w, int kc, int kth) {
    asm("{.reg .pred p; .reg .b64 d0, d1;\n\t"
        "setp.lt.s32 p, %6, %7;\n\t"
        "@p fma.rn.f32x2 d0, %3, %5, %2;\n\t"
        "@p fma.rn.f32x2 d1, %4, %5, %2;\n\t"
        "@p fma.rn.f32x2 %0, d0, d0, %0;\n\t"
        "@p fma.rn.f32x2 %1, d1, d1, %1;}\n"
        : "+l"(A0), "+l"(A1)
        : "l"(w), "l"(b0), "l"(b1), "l"(NEG1C), "r"(kc), "r"(kth));
}
__device__ __forceinline__ void g3(ull& A0, ull& A1, ull& A2,
                                   ull b0, ull b1, ull b2,
                                   ull w, int kc, int kth) {
    asm("{.reg .pred p; .reg .b64 d0, d1, d2;\n\t"
        "setp.lt.s32 p, %8, %9;\n\t"
        "@p fma.rn.f32x2 d0, %4, %7, %3;\n\t"
        "@p fma.rn.f32x2 d1, %5, %7, %3;\n\t"
        "@p fma.rn.f32x2 d2, %6, %7, %3;\n\t"
        "@p fma.rn.f32x2 %0, d0, d0, %0;\n\t"
        "@p fma.rn.f32x2 %1, d1, d1, %1;\n\t"
        "@p fma.rn.f32x2 %2, d2, d2, %2;}\n"
        : "+l"(A0), "+l"(A1), "+l"(A2)
        : "l"(w), "l"(b0), "l"(b1), "l"(b2), "l"(NEG1C), "r"(kc), "r"(kth));
}
__device__ __forceinline__ void g4(ull& A0, ull& A1, ull& A2, ull& A3,
                                   ull b0, ull b1, ull b2, ull b3,
                                   ull w, int kc, int kth) {
    asm("{.reg .pred p; .reg .b64 d0, d1, d2, d3;\n\t"
        "setp.lt.s32 p, %10, %11;\n\t"
        "@p fma.rn.f32x2 d0, %5, %9, %4;\n\t"
        "@p fma.rn.f32x2 d1, %6, %9, %4;\n\t"
        "@p fma.rn.f32x2 d2, %7, %9, %4;\n\t"
        "@p fma.rn.f32x2 d3, %8, %9, %4;\n\t"
        "@p fma.rn.f32x2 %0, d0, d0, %0;\n\t"
        "@p fma.rn.f32x2 %1, d1, d1, %1;\n\t"
        "@p fma.rn.f32x2 %2, d2, d2, %2;\n\t"
        "@p fma.rn.f32x2 %3, d3, d3, %3;}\n"
        : "+l"(A0), "+l"(A1), "+l"(A2), "+l"(A3)
        : "l"(w), "l"(b0), "l"(b1), "l"(b2), "l"(b3), "l"(NEG1C),
          "r"(kc), "r"(kth));
}

__device__ __forceinline__ float block_reduce_256(float v, float* wsum, int tid)
{
    #pragma unroll
    for (int o = 16; o > 0; o >>= 1)
        v += __shfl_down_sync(0xFFFFFFFFu, v, o);
    if ((tid & 31) == 0) wsum[tid >> 5] = v;
    __syncthreads();
    float t = (tid < 8) ? wsum[tid] : 0.f;
    if (tid < 8) {
        #pragma unroll
        for (int o = 4; o > 0; o >>= 1)
            t += __shfl_down_sync(0xFFu, t, o);
        if (tid == 0) wsum[0] = t;
    }
    __syncthreads();
    float r = wsum[0];
    __syncthreads();
    return r;
}

__global__ __launch_bounds__(256, 5)
void physics_loss_fused(const float* __restrict__ alpha_pred,
                        const ull* __restrict__ traj,     // float2 as u64
                        const unsigned int* __restrict__ lens,
                        float* __restrict__ out)
{
    __shared__ ull   sx[SWIN];                 // swizzled window
    __shared__ float sred[NWARP][MAXLAG];      // per-warp lag partials
    __shared__ float wsum[8];
    __shared__ unsigned int s_flag;

    const int b    = blockIdx.x;
    const int cb   = blockIdx.y;
    const int tid  = threadIdx.x;
    const int lane = tid & 31;
    const int warp = tid >> 5;
    const int P0   = cb * BLKP;                // block's first position

    // ---- Stage window [P0, P0+SWIN) of row b (clamped; OOB is masked) ----
    {
        const ull* g = traj + (size_t)b * NT;
        int i0 = P0 + tid;
        sx[swz(tid)] = g[i0 < NT ? i0 : NT - 1];
        if (tid < SWIN - 256) {
            int i1 = P0 + tid + 256;
            sx[swz(tid + 256)] = g[i1 < NT ? i1 : NT - 1];
        }
    }
    __syncthreads();

    const int L = load_length(lens, b);

    // ---- Branch-free register-tiled MSD: thread = 8 lags x 8 positions ----
    const int pw   = warp * POSW;              // warp's first position (local)
    const int lt1  = 8 * lane + 1;             // first lag of this thread
    const int base = pw + lt1;                 // local idx of k=0 endpoint
    const int kth  = L - (P0 + base);          // pair k=i+j valid iff k < kth

    ull acc[8] = {0, 0, 0, 0, 0, 0, 0, 0};

    if (L > P0 + pw + 1) {                     // warp-uniform: any work at all?
        const ull a0 = sx[swz(pw + 0)];        // uniform -> LDS broadcast
        const ull a1 = sx[swz(pw + 1)];
        const ull a2 = sx[swz(pw + 2)];
        const ull a3 = sx[swz(pw + 3)];
        const ull a4 = sx[swz(pw + 4)];
        const ull a5 = sx[swz(pw + 5)];
        const ull a6 = sx[swz(pw + 6)];
        const ull a7 = sx[swz(pw + 7)];

        ull w;
        w = sx[swz(base + 0)];  g1(acc[0], a0, w, 0, kth);
        w = sx[swz(base + 1)];  g2(acc[1], acc[0], a0, a1, w, 1, kth);
        w = sx[swz(base + 2)];  g3(acc[2], acc[1], acc[0], a0, a1, a2, w, 2, kth);
        w = sx[swz(base + 3)];  g4(acc[3], acc[2], acc[1], acc[0], a0, a1, a2, a3, w, 3, kth);
        w = sx[swz(base + 4)];  g4(acc[4], acc[3], acc[2], acc[1], a0, a1, a2, a3, w, 4, kth);
                                g1(acc[0], a4, w, 4, kth);
        w = sx[swz(base + 5)];  g4(acc[5], acc[4], acc[3], acc[2], a0, a1, a2, a3, w, 5, kth);
                                g2(acc[1], acc[0], a4, a5, w, 5, kth);
        w = sx[swz(base + 6)];  g4(acc[6], acc[5], acc[4], acc[3], a0, a1, a2, a3, w, 6, kth);
                                g3(acc[2], acc[1], acc[0], a4, a5, a6, w, 6, kth);
        w = sx[swz(base + 7)];  g4(acc[7], acc[6], acc[5], acc[4], a0, a1, a2, a3, w, 7, kth);
                                g4(acc[3], acc[2], acc[1], acc[0], a4, a5, a6, a7, w, 7, kth);
        w = sx[swz(base + 8)];  g4(acc[7], acc[6], acc[5], acc[4], a1, a2, a3, a4, w, 8, kth);
                                g3(acc[3], acc[2], acc[1], a5, a6, a7, w, 8, kth);
        w = sx[swz(base + 9)];  g4(acc[7], acc[6], acc[5], acc[4], a2, a3, a4, a5, w, 9, kth);
                                g2(acc[3], acc[2], a6, a7, w, 9, kth);
        w = sx[swz(base + 10)]; g4(acc[7], acc[6], acc[5], acc[4], a3, a4, a5, a6, w, 10, kth);
                                g1(acc[3], a7, w, 10, kth);
        w = sx[swz(base + 11)]; g4(acc[7], acc[6], acc[5], acc[4], a4, a5, a6, a7, w, 11, kth);
        w = sx[swz(base + 12)]; g3(acc[7], acc[6], acc[5], a5, a6, a7, w, 12, kth);
        w = sx[swz(base + 13)]; g2(acc[7], acc[6], a6, a7, w, 13, kth);
        w = sx[swz(base + 14)]; g1(acc[7], a7, w, 14, kth);
    }

    // ---- Cross-warp reduction in smem: one partial per lag per block ----
    {
        float r[8];
        #pragma unroll
        for (int j = 0; j < 8; ++j) {
            float2 v = *(float2*)&acc[j];
            r[j] = v.x + v.y;
        }
        float* row = &sred[warp][8 * lane];
        ((float4*)row)[0] = make_float4(r[0], r[1], r[2], r[3]);
        ((float4*)row)[1] = make_float4(r[4], r[5], r[6], r[7]);
    }
    __syncthreads();
    {
        float t = 0.f;
        #pragma unroll
        for (int ww = 0; ww < NWARP; ++ww) t += sred[ww][tid];
        g_partial[((size_t)b * CBLK + cb) * MAXLAG + tid] = t;   // coalesced
    }

    // ---- Last block of batch b performs the regression ----
    if (tid == 0) {
        unsigned int old = atom_inc_acqrel(&g_cnt[b]);   // release: orders STG
        s_flag = (old == CBLK - 1) ? 1u : 0u;
        if (s_flag) g_cnt[b] = 0u;             // reset for graph replay
    }
    __syncthreads();
    if (!s_flag) return;

    float S0 = 0.f, S1 = 0.f, S2 = 0.f, S3 = 0.f;
    {
        const float* pp = &g_partial[(size_t)b * CBLK * MAXLAG + tid];
        #pragma unroll
        for (int cc = 0; cc < CBLK; cc += 4) {
            S0 += __ldcg(&pp[(cc + 0) * MAXLAG]);
            S1 += __ldcg(&pp[(cc + 1) * MAXLAG]);
            S2 += __ldcg(&pp[(cc + 2) * MAXLAG]);
            S3 += __ldcg(&pp[(cc + 3) * MAXLAG]);
        }
    }
    const float S = (S0 + S1) + (S2 + S3);

    const int   l       = tid + 1;
    const int   n       = L - l;
    const float cnt     = fmaxf((float)(n > 0 ? n : 0), 1.0f);
    const float msd     = S / cnt;
    const float log_msd = logf(msd + 1e-8f);
    const float mask    = (L > l) ? 1.f : 0.f;
    const float alpha   = alpha_pred[b];
    const float resid   = log_msd - alpha * logf((float)l);

    int nm = L - 1; if (nm > MAXLAG) nm = MAXLAG; if (nm < 0) nm = 0;
    const float denom = fmaxf((float)nm, 1.0f);

    const float sum_resid = block_reduce_256(resid * mask, wsum, tid);
    const float intercept = sum_resid / denom;

    const float err   = resid - intercept;
    const float sqerr = block_reduce_256(mask * err * err, wsum, tid);

    // ---- Last regression block performs the final mean ----
    if (tid == 0) {
        g_pt[b] = sqerr / denom;
        unsigned int old2 = atom_inc_acqrel(&g_cnt2);
        s_flag = (old2 == NB - 1) ? 1u : 0u;
        if (s_flag) g_cnt2 = 0u;               // reset for graph replay
    }
    __syncthreads();
    if (!s_flag) return;

    float v = (tid < NB) ? __ldcg(&g_pt[tid]) : 0.f;
    const float total = block_reduce_256(v, wsum, tid);
    if (tid == 0) out[0] = total * (1.0f / (float)NB);
}

extern "C" void kernel_launch(void* const* d_in, const int* in_sizes, int n_in,
                              void* d_out, int out_size)
{
    const float*        alpha = (const float*)d_in[0];
    const ull*          traj  = (const ull*)d_in[1];
    const unsigned int* lens  = (const unsigned int*)d_in[2];
    float*              out   = (float*)d_out;

    physics_loss_fused<<<dim3(NB, CBLK), 256>>>(alpha, traj, lens, out);
}